// round 15
// baseline (speedup 1.0000x reference)
#include <cuda_runtime.h>

// ---------------- scratch (static device globals; no allocation) ----------------
__device__ float g_sig[64 * 4080];          // signature features, (64, 34*120) row-major
__device__ float g_hp[34 * 64 * 512];       // split-K partials of hidden layer

// ---------------- f32x2 packed helpers ----------------
__device__ __forceinline__ unsigned long long ffma2(unsigned long long a,
                                                    unsigned long long b,
                                                    unsigned long long c)
{
    unsigned long long d;
    asm("fma.rn.f32x2 %0, %1, %2, %3;" : "=l"(d) : "l"(a), "l"(b), "l"(c));
    return d;
}
__device__ __forceinline__ unsigned long long pack_dup(float x)
{
    unsigned long long d;
    asm("mov.b64 %0, {%1, %1};" : "=l"(d) : "f"(x));
    return d;
}

// ================= Kernel 1: depth-4 path signature =================
// (exact R13 version — 18.6us measured) 8 paths x 16 chunks, grid 272.
// Factored Chen step (183 FMA); combine levels 0-1 via warp shuffles,
// levels 2-3 via smem with 2 block barriers.

__global__ void __launch_bounds__(128) sig_kernel(const float* __restrict__ inp)
{
    __shared__ float xch[24][121];

    const int tid = threadIdx.x;
    const int pl = tid & 7;
    const int chunk = tid >> 3;
    const int p = blockIdx.x * 8 + pl;
    const int b = p / 34;
    const int vm = p - b * 34;
    const float* base = inp + b * 30600 + vm;

    const int s0 = (chunk * 299) >> 4;
    const int s1 = ((chunk + 1) * 299) >> 4;

    float c1[3], c2[9], c3[27], c4[81];
#pragma unroll
    for (int i = 0; i < 3; i++) c1[i] = 0.f;
#pragma unroll
    for (int i = 0; i < 9; i++) c2[i] = 0.f;
#pragma unroll
    for (int i = 0; i < 27; i++) c3[i] = 0.f;
#pragma unroll
    for (int i = 0; i < 81; i++) c4[i] = 0.f;

    float xp[3], xc[3];
#pragma unroll
    for (int c = 0; c < 3; c++) xp[c] = __ldg(base + c * 10200 + s0 * 34);
#pragma unroll
    for (int c = 0; c < 3; c++) xc[c] = __ldg(base + c * 10200 + (s0 + 1) * 34);

    for (int s = s0; s < s1; ++s) {
        int tn = s + 2; if (tn > 299) tn = 299;
        float xn[3];
#pragma unroll
        for (int c = 0; c < 3; c++) xn[c] = __ldg(base + c * 10200 + tn * 34);

        float dx[3], dxh[3], dx3[3], e[3], bq[3], a[3];
#pragma unroll
        for (int i = 0; i < 3; i++) {
            dx[i]  = xc[i] - xp[i];
            dxh[i] = 0.5f * dx[i];
            dx3[i] = (1.0f / 3.0f) * dx[i];
            e[i]  = fmaf(0.25f, dx[i], c1[i]);
            bq[i] = c1[i] + dx3[i];
            a[i]  = c1[i] + dxh[i];
        }
        float q[9], sx[9];
#pragma unroll
        for (int i = 0; i < 3; i++)
#pragma unroll
            for (int j = 0; j < 3; j++) {
                q[i * 3 + j]  = fmaf(e[i],  dx3[j], c2[i * 3 + j]);
                sx[i * 3 + j] = fmaf(bq[i], dxh[j], c2[i * 3 + j]);
            }
#pragma unroll
        for (int i = 0; i < 3; i++)
#pragma unroll
            for (int j = 0; j < 3; j++)
#pragma unroll
                for (int k = 0; k < 3; k++) {
                    const float r = fmaf(q[i * 3 + j], dxh[k], c3[i * 9 + j * 3 + k]);
                    const int x0 = i * 27 + j * 9 + k * 3;
#pragma unroll
                    for (int l = 0; l < 3; l++)
                        c4[x0 + l] = fmaf(r, dx[l], c4[x0 + l]);
                }
#pragma unroll
        for (int i = 0; i < 3; i++)
#pragma unroll
            for (int j = 0; j < 3; j++)
#pragma unroll
                for (int k = 0; k < 3; k++) {
                    const int x = i * 9 + j * 3 + k;
                    c3[x] = fmaf(sx[i * 3 + j], dx[k], c3[x]);
                }
#pragma unroll
        for (int i = 0; i < 3; i++)
#pragma unroll
            for (int j = 0; j < 3; j++)
                c2[i * 3 + j] = fmaf(a[i], dx[j], c2[i * 3 + j]);
#pragma unroll
        for (int i = 0; i < 3; i++) c1[i] += dx[i];

#pragma unroll
        for (int c = 0; c < 3; c++) { xp[c] = xc[c]; xc[c] = xn[c]; }
    }

    // ---- levels 0-1: shuffle combine (partner = +8, +16 lanes; same warp) ----
#pragma unroll
    for (int d = 0; d < 2; d++) {
        const unsigned delta = 8u << d;
        float bb1[3], bb2[9], bb3[27];
#pragma unroll
        for (int i = 0; i < 3; i++)  bb1[i] = __shfl_down_sync(0xffffffffu, c1[i], delta);
#pragma unroll
        for (int i = 0; i < 9; i++)  bb2[i] = __shfl_down_sync(0xffffffffu, c2[i], delta);
#pragma unroll
        for (int i = 0; i < 27; i++) bb3[i] = __shfl_down_sync(0xffffffffu, c3[i], delta);

#pragma unroll
        for (int i = 0; i < 3; i++)
#pragma unroll
            for (int j = 0; j < 3; j++)
#pragma unroll
                for (int k = 0; k < 3; k++)
#pragma unroll
                    for (int l = 0; l < 3; l++) {
                        const int x = i * 27 + j * 9 + k * 3 + l;
                        const float b4 = __shfl_down_sync(0xffffffffu, c4[x], delta);
                        c4[x] = fmaf(c3[i * 9 + j * 3 + k], bb1[l],
                                fmaf(c2[i * 3 + j], bb2[k * 3 + l],
                                fmaf(c1[i], bb3[j * 9 + k * 3 + l],
                                     c4[x] + b4)));
                    }
#pragma unroll
        for (int i = 0; i < 3; i++)
#pragma unroll
            for (int j = 0; j < 3; j++)
#pragma unroll
                for (int k = 0; k < 3; k++) {
                    const int x = i * 9 + j * 3 + k;
                    c3[x] = fmaf(c2[i * 3 + j], bb1[k],
                            fmaf(c1[i], bb2[j * 3 + k], c3[x] + bb3[x]));
                }
#pragma unroll
        for (int i = 0; i < 3; i++)
#pragma unroll
            for (int j = 0; j < 3; j++)
                c2[i * 3 + j] = fmaf(c1[i], bb1[j], c2[i * 3 + j] + bb2[i * 3 + j]);
#pragma unroll
        for (int i = 0; i < 3; i++) c1[i] += bb1[i];
    }

    // ---- levels 2-3 via smem. Survivors: lanes 0-7 of each warp (chunk=4w). ----
    const int w = tid >> 5;
    const bool lane8 = (tid & 31) < 8;

    if (lane8 && (w & 1)) {                 // level-2 writers: warps 1,3
        float* wr = xch[pl + 8 * (w >> 1)];
#pragma unroll
        for (int i = 0; i < 3; i++) wr[i] = c1[i];
#pragma unroll
        for (int i = 0; i < 9; i++) wr[3 + i] = c2[i];
#pragma unroll
        for (int i = 0; i < 27; i++) wr[12 + i] = c3[i];
#pragma unroll
        for (int i = 0; i < 81; i++) wr[39 + i] = c4[i];
    }
    __syncthreads();
    if (lane8 && !(w & 1)) {                // level-2 readers: warps 0,2
        const float* B = xch[pl + 8 * (w >> 1)];
        float bb1[3], bb2[9], bb3[27];
#pragma unroll
        for (int i = 0; i < 3; i++) bb1[i] = B[i];
#pragma unroll
        for (int i = 0; i < 9; i++) bb2[i] = B[3 + i];
#pragma unroll
        for (int i = 0; i < 27; i++) bb3[i] = B[12 + i];
#pragma unroll
        for (int i = 0; i < 3; i++)
#pragma unroll
            for (int j = 0; j < 3; j++)
#pragma unroll
                for (int k = 0; k < 3; k++)
#pragma unroll
                    for (int l = 0; l < 3; l++) {
                        const int x = i * 27 + j * 9 + k * 3 + l;
                        c4[x] = fmaf(c3[i * 9 + j * 3 + k], bb1[l],
                                fmaf(c2[i * 3 + j], bb2[k * 3 + l],
                                fmaf(c1[i], bb3[j * 9 + k * 3 + l],
                                     c4[x] + B[39 + x])));
                    }
#pragma unroll
        for (int i = 0; i < 3; i++)
#pragma unroll
            for (int j = 0; j < 3; j++)
#pragma unroll
                for (int k = 0; k < 3; k++) {
                    const int x = i * 9 + j * 3 + k;
                    c3[x] = fmaf(c2[i * 3 + j], bb1[k],
                            fmaf(c1[i], bb2[j * 3 + k], c3[x] + bb3[x]));
                }
#pragma unroll
        for (int i = 0; i < 3; i++)
#pragma unroll
            for (int j = 0; j < 3; j++)
                c2[i * 3 + j] = fmaf(c1[i], bb1[j], c2[i * 3 + j] + bb2[i * 3 + j]);
#pragma unroll
        for (int i = 0; i < 3; i++) c1[i] += bb1[i];
    }
    if (lane8 && w == 2) {                  // level-3 writer: warp 2
        float* wr = xch[16 + pl];
#pragma unroll
        for (int i = 0; i < 3; i++) wr[i] = c1[i];
#pragma unroll
        for (int i = 0; i < 9; i++) wr[3 + i] = c2[i];
#pragma unroll
        for (int i = 0; i < 27; i++) wr[12 + i] = c3[i];
#pragma unroll
        for (int i = 0; i < 81; i++) wr[39 + i] = c4[i];
    }
    __syncthreads();
    if (tid < 8) {                          // level-3 reader: warp 0, final store
        const float* B = xch[16 + pl];
        float bb1[3], bb2[9], bb3[27];
#pragma unroll
        for (int i = 0; i < 3; i++) bb1[i] = B[i];
#pragma unroll
        for (int i = 0; i < 9; i++) bb2[i] = B[3 + i];
#pragma unroll
        for (int i = 0; i < 27; i++) bb3[i] = B[12 + i];
#pragma unroll
        for (int i = 0; i < 3; i++)
#pragma unroll
            for (int j = 0; j < 3; j++)
#pragma unroll
                for (int k = 0; k < 3; k++)
#pragma unroll
                    for (int l = 0; l < 3; l++) {
                        const int x = i * 27 + j * 9 + k * 3 + l;
                        c4[x] = fmaf(c3[i * 9 + j * 3 + k], bb1[l],
                                fmaf(c2[i * 3 + j], bb2[k * 3 + l],
                                fmaf(c1[i], bb3[j * 9 + k * 3 + l],
                                     c4[x] + B[39 + x])));
                    }
#pragma unroll
        for (int i = 0; i < 3; i++)
#pragma unroll
            for (int j = 0; j < 3; j++)
#pragma unroll
                for (int k = 0; k < 3; k++) {
                    const int x = i * 9 + j * 3 + k;
                    c3[x] = fmaf(c2[i * 3 + j], bb1[k],
                            fmaf(c1[i], bb2[j * 3 + k], c3[x] + bb3[x]));
                }
#pragma unroll
        for (int i = 0; i < 3; i++)
#pragma unroll
            for (int j = 0; j < 3; j++)
                c2[i * 3 + j] = fmaf(c1[i], bb1[j], c2[i * 3 + j] + bb2[i * 3 + j]);
#pragma unroll
        for (int i = 0; i < 3; i++) c1[i] += bb1[i];

        float* out = g_sig + p * 120;
#pragma unroll
        for (int i = 0; i < 3; i++) out[i] = c1[i];
#pragma unroll
        for (int i = 0; i < 9; i++) out[3 + i] = c2[i];
#pragma unroll
        for (int i = 0; i < 27; i++) out[12 + i] = c3[i];
#pragma unroll
        for (int i = 0; i < 81; i++) out[39 + i] = c4[i];
    }
}

// ================= Kernel 2: h-partials = sig @ W1^T (split-K 34) =================
// (unchanged — measured fast) Full-K staging, one barrier, FFMA2 loop.

__global__ void __launch_bounds__(128) gemm1_kernel(const float* __restrict__ W1)
{
    __shared__ float As[120][68];
    __shared__ float Bs[120][36];

    const int jt = blockIdx.x;
    const int ks = blockIdx.y;
    const int tid = threadIdx.x;
    const int tx = tid & 7;
    const int ty = tid >> 3;
    const int k0 = ks * 120;
    const int j0 = jt * 32;

    {
        const int arow = tid >> 1;
        const int kh = (tid & 1) * 4;
        const float* Ap = g_sig + arow * 4080 + k0 + kh;
#pragma unroll
        for (int it = 0; it < 15; it++) {
            const float4 v = *(const float4*)(Ap + it * 8);
            const int k = it * 8 + kh;
            As[k + 0][arow] = v.x; As[k + 1][arow] = v.y;
            As[k + 2][arow] = v.z; As[k + 3][arow] = v.w;
        }
    }
    {
        const int jrow = (tid >> 1) & 31;
        const int kh = ((tid >> 6) << 3) + (tid & 1) * 4;
        const float* Bp = W1 + (j0 + jrow) * 4080 + k0 + kh;
#pragma unroll
        for (int it = 0; it < 8; it++) {
            const int k = it * 16 + kh;
            if (k < 120) {
                const float4 v = *(const float4*)(Bp + it * 16);
                Bs[k + 0][jrow] = v.x; Bs[k + 1][jrow] = v.y;
                Bs[k + 2][jrow] = v.z; Bs[k + 3][jrow] = v.w;
            }
        }
    }
    __syncthreads();

    unsigned long long accp[4][2];
#pragma unroll
    for (int r = 0; r < 4; r++) { accp[r][0] = 0ull; accp[r][1] = 0ull; }

#pragma unroll 4
    for (int kk = 0; kk < 120; kk++) {
        const float4 a = *(const float4*)&As[kk][ty * 4];
        const ulonglong2 bp = *(const ulonglong2*)&Bs[kk][tx * 4];
        unsigned long long aa;
        aa = pack_dup(a.x);
        accp[0][0] = ffma2(aa, bp.x, accp[0][0]);
        accp[0][1] = ffma2(aa, bp.y, accp[0][1]);
        aa = pack_dup(a.y);
        accp[1][0] = ffma2(aa, bp.x, accp[1][0]);
        accp[1][1] = ffma2(aa, bp.y, accp[1][1]);
        aa = pack_dup(a.z);
        accp[2][0] = ffma2(aa, bp.x, accp[2][0]);
        accp[2][1] = ffma2(aa, bp.y, accp[2][1]);
        aa = pack_dup(a.w);
        accp[3][0] = ffma2(aa, bp.x, accp[3][0]);
        accp[3][1] = ffma2(aa, bp.y, accp[3][1]);
    }

    float* outp = g_hp + ks * 32768 + j0;
#pragma unroll
    for (int r = 0; r < 4; r++) {
        const unsigned long long v0 = accp[r][0], v1 = accp[r][1];
        float4 v;
        v.x = __uint_as_float((unsigned)(v0 & 0xffffffffu));
        v.y = __uint_as_float((unsigned)(v0 >> 32));
        v.z = __uint_as_float((unsigned)(v1 & 0xffffffffu));
        v.w = __uint_as_float((unsigned)(v1 >> 32));
        *(float4*)(outp + (ty * 4 + r) * 512 + tx * 4) = v;
    }
}

// ====== Kernel 3: out = (sum_s hp_s + b1) @ W2^T + b2, grid (64 rows, 5 j-tiles) ======
// Phase-1 reduce now float4: 128 threads x 34 independent float4 loads
// (4x fewer load instructions, same bytes, MLP 34).

__global__ void __launch_bounds__(256) gemm2_kernel(const float* __restrict__ b1,
                                                    const float* __restrict__ W2,
                                                    const float* __restrict__ b2,
                                                    float* __restrict__ out)
{
    __shared__ float hs[512];
    const int i = blockIdx.x;
    const int jt = blockIdx.y;
    const int tid = threadIdx.x;

    if (tid < 128) {
        const float4* hp = (const float4*)(g_hp + i * 512) + tid;
        float4 a = ((const float4*)b1)[tid];
#pragma unroll
        for (int s = 0; s < 34; s++) {
            const float4 v = hp[s * 8192];          // 32768 floats = 8192 float4
            a.x += v.x; a.y += v.y; a.z += v.z; a.w += v.w;
        }
        ((float4*)hs)[tid] = a;
    }
    __syncthreads();

    const int jl = tid >> 3;
    const int ell = tid & 7;
    if (jl < 31) {
        const int j = jt * 31 + jl;
        const float4* w = (const float4*)(W2 + j * 512) + ell;
        float acc0 = 0.f, acc1 = 0.f;
#pragma unroll
        for (int it = 0; it < 16; it += 2) {
            const float4 w0 = w[it * 8];
            const float4 w1 = w[(it + 1) * 8];
            const float* h0 = &hs[(ell + it * 8) * 4];
            const float* h1 = &hs[(ell + (it + 1) * 8) * 4];
            acc0 = fmaf(h0[0], w0.x, acc0); acc0 = fmaf(h0[1], w0.y, acc0);
            acc0 = fmaf(h0[2], w0.z, acc0); acc0 = fmaf(h0[3], w0.w, acc0);
            acc1 = fmaf(h1[0], w1.x, acc1); acc1 = fmaf(h1[1], w1.y, acc1);
            acc1 = fmaf(h1[2], w1.z, acc1); acc1 = fmaf(h1[3], w1.w, acc1);
        }
        float acc = acc0 + acc1;
#pragma unroll
        for (int m = 1; m < 8; m <<= 1)
            acc += __shfl_xor_sync(0xffffffffu, acc, m);
        if (ell == 0) out[i * 155 + j] = acc + b2[j];
    }
}

// ================================ launch =================================

extern "C" void kernel_launch(void* const* d_in, const int* in_sizes, int n_in,
                              void* d_out, int out_size)
{
    const float* inp = (const float*)d_in[0];
    const float* W1  = (const float*)d_in[1];
    const float* b1  = (const float*)d_in[2];
    const float* W2  = (const float*)d_in[3];
    const float* b2  = (const float*)d_in[4];
    float* out = (float*)d_out;

    sig_kernel<<<272, 128>>>(inp);
    gemm1_kernel<<<dim3(16, 34), 128>>>(W1);
    gemm2_kernel<<<dim3(64, 5), 256>>>(b1, W2, b2, out);
}

// round 16
// speedup vs baseline: 1.0058x; 1.0058x over previous
#include <cuda_runtime.h>

// ---------------- scratch (static device globals; no allocation) ----------------
__device__ float g_sig[64 * 4080];          // signature features, (64, 34*120) row-major
__device__ float g_hp[34 * 64 * 512];       // split-K partials of hidden layer

// ---------------- f32x2 packed helpers ----------------
__device__ __forceinline__ unsigned long long ffma2(unsigned long long a,
                                                    unsigned long long b,
                                                    unsigned long long c)
{
    unsigned long long d;
    asm("fma.rn.f32x2 %0, %1, %2, %3;" : "=l"(d) : "l"(a), "l"(b), "l"(c));
    return d;
}
__device__ __forceinline__ unsigned long long pack_dup(float x)
{
    unsigned long long d;
    asm("mov.b64 %0, {%1, %1};" : "=l"(d) : "f"(x));
    return d;
}

// ================= Kernel 1: depth-4 path signature =================
// (exact R13 version — 18.6us on fast node) 8 paths x 16 chunks, grid 272.
// Factored Chen step (183 FMA); combine levels 0-1 via warp shuffles,
// levels 2-3 via smem with 2 block barriers.

__global__ void __launch_bounds__(128) sig_kernel(const float* __restrict__ inp)
{
    __shared__ float xch[24][121];

    const int tid = threadIdx.x;
    const int pl = tid & 7;
    const int chunk = tid >> 3;
    const int p = blockIdx.x * 8 + pl;
    const int b = p / 34;
    const int vm = p - b * 34;
    const float* base = inp + b * 30600 + vm;

    const int s0 = (chunk * 299) >> 4;
    const int s1 = ((chunk + 1) * 299) >> 4;

    float c1[3], c2[9], c3[27], c4[81];
#pragma unroll
    for (int i = 0; i < 3; i++) c1[i] = 0.f;
#pragma unroll
    for (int i = 0; i < 9; i++) c2[i] = 0.f;
#pragma unroll
    for (int i = 0; i < 27; i++) c3[i] = 0.f;
#pragma unroll
    for (int i = 0; i < 81; i++) c4[i] = 0.f;

    float xp[3], xc[3];
#pragma unroll
    for (int c = 0; c < 3; c++) xp[c] = __ldg(base + c * 10200 + s0 * 34);
#pragma unroll
    for (int c = 0; c < 3; c++) xc[c] = __ldg(base + c * 10200 + (s0 + 1) * 34);

    for (int s = s0; s < s1; ++s) {
        int tn = s + 2; if (tn > 299) tn = 299;
        float xn[3];
#pragma unroll
        for (int c = 0; c < 3; c++) xn[c] = __ldg(base + c * 10200 + tn * 34);

        float dx[3], dxh[3], dx3[3], e[3], bq[3], a[3];
#pragma unroll
        for (int i = 0; i < 3; i++) {
            dx[i]  = xc[i] - xp[i];
            dxh[i] = 0.5f * dx[i];
            dx3[i] = (1.0f / 3.0f) * dx[i];
            e[i]  = fmaf(0.25f, dx[i], c1[i]);
            bq[i] = c1[i] + dx3[i];
            a[i]  = c1[i] + dxh[i];
        }
        float q[9], sx[9];
#pragma unroll
        for (int i = 0; i < 3; i++)
#pragma unroll
            for (int j = 0; j < 3; j++) {
                q[i * 3 + j]  = fmaf(e[i],  dx3[j], c2[i * 3 + j]);
                sx[i * 3 + j] = fmaf(bq[i], dxh[j], c2[i * 3 + j]);
            }
#pragma unroll
        for (int i = 0; i < 3; i++)
#pragma unroll
            for (int j = 0; j < 3; j++)
#pragma unroll
                for (int k = 0; k < 3; k++) {
                    const float r = fmaf(q[i * 3 + j], dxh[k], c3[i * 9 + j * 3 + k]);
                    const int x0 = i * 27 + j * 9 + k * 3;
#pragma unroll
                    for (int l = 0; l < 3; l++)
                        c4[x0 + l] = fmaf(r, dx[l], c4[x0 + l]);
                }
#pragma unroll
        for (int i = 0; i < 3; i++)
#pragma unroll
            for (int j = 0; j < 3; j++)
#pragma unroll
                for (int k = 0; k < 3; k++) {
                    const int x = i * 9 + j * 3 + k;
                    c3[x] = fmaf(sx[i * 3 + j], dx[k], c3[x]);
                }
#pragma unroll
        for (int i = 0; i < 3; i++)
#pragma unroll
            for (int j = 0; j < 3; j++)
                c2[i * 3 + j] = fmaf(a[i], dx[j], c2[i * 3 + j]);
#pragma unroll
        for (int i = 0; i < 3; i++) c1[i] += dx[i];

#pragma unroll
        for (int c = 0; c < 3; c++) { xp[c] = xc[c]; xc[c] = xn[c]; }
    }

    // ---- levels 0-1: shuffle combine (partner = +8, +16 lanes; same warp) ----
#pragma unroll
    for (int d = 0; d < 2; d++) {
        const unsigned delta = 8u << d;
        float bb1[3], bb2[9], bb3[27];
#pragma unroll
        for (int i = 0; i < 3; i++)  bb1[i] = __shfl_down_sync(0xffffffffu, c1[i], delta);
#pragma unroll
        for (int i = 0; i < 9; i++)  bb2[i] = __shfl_down_sync(0xffffffffu, c2[i], delta);
#pragma unroll
        for (int i = 0; i < 27; i++) bb3[i] = __shfl_down_sync(0xffffffffu, c3[i], delta);

#pragma unroll
        for (int i = 0; i < 3; i++)
#pragma unroll
            for (int j = 0; j < 3; j++)
#pragma unroll
                for (int k = 0; k < 3; k++)
#pragma unroll
                    for (int l = 0; l < 3; l++) {
                        const int x = i * 27 + j * 9 + k * 3 + l;
                        const float b4 = __shfl_down_sync(0xffffffffu, c4[x], delta);
                        c4[x] = fmaf(c3[i * 9 + j * 3 + k], bb1[l],
                                fmaf(c2[i * 3 + j], bb2[k * 3 + l],
                                fmaf(c1[i], bb3[j * 9 + k * 3 + l],
                                     c4[x] + b4)));
                    }
#pragma unroll
        for (int i = 0; i < 3; i++)
#pragma unroll
            for (int j = 0; j < 3; j++)
#pragma unroll
                for (int k = 0; k < 3; k++) {
                    const int x = i * 9 + j * 3 + k;
                    c3[x] = fmaf(c2[i * 3 + j], bb1[k],
                            fmaf(c1[i], bb2[j * 3 + k], c3[x] + bb3[x]));
                }
#pragma unroll
        for (int i = 0; i < 3; i++)
#pragma unroll
            for (int j = 0; j < 3; j++)
                c2[i * 3 + j] = fmaf(c1[i], bb1[j], c2[i * 3 + j] + bb2[i * 3 + j]);
#pragma unroll
        for (int i = 0; i < 3; i++) c1[i] += bb1[i];
    }

    // ---- levels 2-3 via smem. Survivors: lanes 0-7 of each warp (chunk=4w). ----
    const int w = tid >> 5;
    const bool lane8 = (tid & 31) < 8;

    if (lane8 && (w & 1)) {                 // level-2 writers: warps 1,3
        float* wr = xch[pl + 8 * (w >> 1)];
#pragma unroll
        for (int i = 0; i < 3; i++) wr[i] = c1[i];
#pragma unroll
        for (int i = 0; i < 9; i++) wr[3 + i] = c2[i];
#pragma unroll
        for (int i = 0; i < 27; i++) wr[12 + i] = c3[i];
#pragma unroll
        for (int i = 0; i < 81; i++) wr[39 + i] = c4[i];
    }
    __syncthreads();
    if (lane8 && !(w & 1)) {                // level-2 readers: warps 0,2
        const float* B = xch[pl + 8 * (w >> 1)];
        float bb1[3], bb2[9], bb3[27];
#pragma unroll
        for (int i = 0; i < 3; i++) bb1[i] = B[i];
#pragma unroll
        for (int i = 0; i < 9; i++) bb2[i] = B[3 + i];
#pragma unroll
        for (int i = 0; i < 27; i++) bb3[i] = B[12 + i];
#pragma unroll
        for (int i = 0; i < 3; i++)
#pragma unroll
            for (int j = 0; j < 3; j++)
#pragma unroll
                for (int k = 0; k < 3; k++)
#pragma unroll
                    for (int l = 0; l < 3; l++) {
                        const int x = i * 27 + j * 9 + k * 3 + l;
                        c4[x] = fmaf(c3[i * 9 + j * 3 + k], bb1[l],
                                fmaf(c2[i * 3 + j], bb2[k * 3 + l],
                                fmaf(c1[i], bb3[j * 9 + k * 3 + l],
                                     c4[x] + B[39 + x])));
                    }
#pragma unroll
        for (int i = 0; i < 3; i++)
#pragma unroll
            for (int j = 0; j < 3; j++)
#pragma unroll
                for (int k = 0; k < 3; k++) {
                    const int x = i * 9 + j * 3 + k;
                    c3[x] = fmaf(c2[i * 3 + j], bb1[k],
                            fmaf(c1[i], bb2[j * 3 + k], c3[x] + bb3[x]));
                }
#pragma unroll
        for (int i = 0; i < 3; i++)
#pragma unroll
            for (int j = 0; j < 3; j++)
                c2[i * 3 + j] = fmaf(c1[i], bb1[j], c2[i * 3 + j] + bb2[i * 3 + j]);
#pragma unroll
        for (int i = 0; i < 3; i++) c1[i] += bb1[i];
    }
    if (lane8 && w == 2) {                  // level-3 writer: warp 2
        float* wr = xch[16 + pl];
#pragma unroll
        for (int i = 0; i < 3; i++) wr[i] = c1[i];
#pragma unroll
        for (int i = 0; i < 9; i++) wr[3 + i] = c2[i];
#pragma unroll
        for (int i = 0; i < 27; i++) wr[12 + i] = c3[i];
#pragma unroll
        for (int i = 0; i < 81; i++) wr[39 + i] = c4[i];
    }
    __syncthreads();
    if (tid < 8) {                          // level-3 reader: warp 0, final store
        const float* B = xch[16 + pl];
        float bb1[3], bb2[9], bb3[27];
#pragma unroll
        for (int i = 0; i < 3; i++) bb1[i] = B[i];
#pragma unroll
        for (int i = 0; i < 9; i++) bb2[i] = B[3 + i];
#pragma unroll
        for (int i = 0; i < 27; i++) bb3[i] = B[12 + i];
#pragma unroll
        for (int i = 0; i < 3; i++)
#pragma unroll
            for (int j = 0; j < 3; j++)
#pragma unroll
                for (int k = 0; k < 3; k++)
#pragma unroll
                    for (int l = 0; l < 3; l++) {
                        const int x = i * 27 + j * 9 + k * 3 + l;
                        c4[x] = fmaf(c3[i * 9 + j * 3 + k], bb1[l],
                                fmaf(c2[i * 3 + j], bb2[k * 3 + l],
                                fmaf(c1[i], bb3[j * 9 + k * 3 + l],
                                     c4[x] + B[39 + x])));
                    }
#pragma unroll
        for (int i = 0; i < 3; i++)
#pragma unroll
            for (int j = 0; j < 3; j++)
#pragma unroll
                for (int k = 0; k < 3; k++) {
                    const int x = i * 9 + j * 3 + k;
                    c3[x] = fmaf(c2[i * 3 + j], bb1[k],
                            fmaf(c1[i], bb2[j * 3 + k], c3[x] + bb3[x]));
                }
#pragma unroll
        for (int i = 0; i < 3; i++)
#pragma unroll
            for (int j = 0; j < 3; j++)
                c2[i * 3 + j] = fmaf(c1[i], bb1[j], c2[i * 3 + j] + bb2[i * 3 + j]);
#pragma unroll
        for (int i = 0; i < 3; i++) c1[i] += bb1[i];

        float* out = g_sig + p * 120;
#pragma unroll
        for (int i = 0; i < 3; i++) out[i] = c1[i];
#pragma unroll
        for (int i = 0; i < 9; i++) out[3 + i] = c2[i];
#pragma unroll
        for (int i = 0; i < 27; i++) out[12 + i] = c3[i];
#pragma unroll
        for (int i = 0; i < 81; i++) out[39 + i] = c4[i];
    }
}

// ================= Kernel 2: h-partials = sig @ W1^T (split-K 34) =================
// (unchanged — measured fast) Full-K staging, one barrier, FFMA2 loop.

__global__ void __launch_bounds__(128) gemm1_kernel(const float* __restrict__ W1)
{
    __shared__ float As[120][68];
    __shared__ float Bs[120][36];

    const int jt = blockIdx.x;
    const int ks = blockIdx.y;
    const int tid = threadIdx.x;
    const int tx = tid & 7;
    const int ty = tid >> 3;
    const int k0 = ks * 120;
    const int j0 = jt * 32;

    {
        const int arow = tid >> 1;
        const int kh = (tid & 1) * 4;
        const float* Ap = g_sig + arow * 4080 + k0 + kh;
#pragma unroll
        for (int it = 0; it < 15; it++) {
            const float4 v = *(const float4*)(Ap + it * 8);
            const int k = it * 8 + kh;
            As[k + 0][arow] = v.x; As[k + 1][arow] = v.y;
            As[k + 2][arow] = v.z; As[k + 3][arow] = v.w;
        }
    }
    {
        const int jrow = (tid >> 1) & 31;
        const int kh = ((tid >> 6) << 3) + (tid & 1) * 4;
        const float* Bp = W1 + (j0 + jrow) * 4080 + k0 + kh;
#pragma unroll
        for (int it = 0; it < 8; it++) {
            const int k = it * 16 + kh;
            if (k < 120) {
                const float4 v = *(const float4*)(Bp + it * 16);
                Bs[k + 0][jrow] = v.x; Bs[k + 1][jrow] = v.y;
                Bs[k + 2][jrow] = v.z; Bs[k + 3][jrow] = v.w;
            }
        }
    }
    __syncthreads();

    unsigned long long accp[4][2];
#pragma unroll
    for (int r = 0; r < 4; r++) { accp[r][0] = 0ull; accp[r][1] = 0ull; }

#pragma unroll 4
    for (int kk = 0; kk < 120; kk++) {
        const float4 a = *(const float4*)&As[kk][ty * 4];
        const ulonglong2 bp = *(const ulonglong2*)&Bs[kk][tx * 4];
        unsigned long long aa;
        aa = pack_dup(a.x);
        accp[0][0] = ffma2(aa, bp.x, accp[0][0]);
        accp[0][1] = ffma2(aa, bp.y, accp[0][1]);
        aa = pack_dup(a.y);
        accp[1][0] = ffma2(aa, bp.x, accp[1][0]);
        accp[1][1] = ffma2(aa, bp.y, accp[1][1]);
        aa = pack_dup(a.z);
        accp[2][0] = ffma2(aa, bp.x, accp[2][0]);
        accp[2][1] = ffma2(aa, bp.y, accp[2][1]);
        aa = pack_dup(a.w);
        accp[3][0] = ffma2(aa, bp.x, accp[3][0]);
        accp[3][1] = ffma2(aa, bp.y, accp[3][1]);
    }

    float* outp = g_hp + ks * 32768 + j0;
#pragma unroll
    for (int r = 0; r < 4; r++) {
        const unsigned long long v0 = accp[r][0], v1 = accp[r][1];
        float4 v;
        v.x = __uint_as_float((unsigned)(v0 & 0xffffffffu));
        v.y = __uint_as_float((unsigned)(v0 >> 32));
        v.z = __uint_as_float((unsigned)(v1 & 0xffffffffu));
        v.w = __uint_as_float((unsigned)(v1 >> 32));
        *(float4*)(outp + (ty * 4 + r) * 512 + tx * 4) = v;
    }
}

// ====== Kernel 3: out = (sum_s hp_s + b1) @ W2^T + b2, grid (64 rows, 5 j-tiles) ======
// Phase-1 reduce float4: 128 threads x 34 independent float4 loads
// (4x fewer load instructions, same bytes, MLP 34).

__global__ void __launch_bounds__(256) gemm2_kernel(const float* __restrict__ b1,
                                                    const float* __restrict__ W2,
                                                    const float* __restrict__ b2,
                                                    float* __restrict__ out)
{
    __shared__ float hs[512];
    const int i = blockIdx.x;
    const int jt = blockIdx.y;
    const int tid = threadIdx.x;

    if (tid < 128) {
        const float4* hp = (const float4*)(g_hp + i * 512) + tid;
        float4 a = ((const float4*)b1)[tid];
#pragma unroll
        for (int s = 0; s < 34; s++) {
            const float4 v = hp[s * 8192];          // 32768 floats = 8192 float4
            a.x += v.x; a.y += v.y; a.z += v.z; a.w += v.w;
        }
        ((float4*)hs)[tid] = a;
    }
    __syncthreads();

    const int jl = tid >> 3;
    const int ell = tid & 7;
    if (jl < 31) {
        const int j = jt * 31 + jl;
        const float4* w = (const float4*)(W2 + j * 512) + ell;
        float acc0 = 0.f, acc1 = 0.f;
#pragma unroll
        for (int it = 0; it < 16; it += 2) {
            const float4 w0 = w[it * 8];
            const float4 w1 = w[(it + 1) * 8];
            const float* h0 = &hs[(ell + it * 8) * 4];
            const float* h1 = &hs[(ell + (it + 1) * 8) * 4];
            acc0 = fmaf(h0[0], w0.x, acc0); acc0 = fmaf(h0[1], w0.y, acc0);
            acc0 = fmaf(h0[2], w0.z, acc0); acc0 = fmaf(h0[3], w0.w, acc0);
            acc1 = fmaf(h1[0], w1.x, acc1); acc1 = fmaf(h1[1], w1.y, acc1);
            acc1 = fmaf(h1[2], w1.z, acc1); acc1 = fmaf(h1[3], w1.w, acc1);
        }
        float acc = acc0 + acc1;
#pragma unroll
        for (int m = 1; m < 8; m <<= 1)
            acc += __shfl_xor_sync(0xffffffffu, acc, m);
        if (ell == 0) out[i * 155 + j] = acc + b2[j];
    }
}

// ================================ launch =================================

extern "C" void kernel_launch(void* const* d_in, const int* in_sizes, int n_in,
                              void* d_out, int out_size)
{
    const float* inp = (const float*)d_in[0];
    const float* W1  = (const float*)d_in[1];
    const float* b1  = (const float*)d_in[2];
    const float* W2  = (const float*)d_in[3];
    const float* b2  = (const float*)d_in[4];
    float* out = (float*)d_out;

    sig_kernel<<<272, 128>>>(inp);
    gemm1_kernel<<<dim3(16, 34), 128>>>(W1);
    gemm2_kernel<<<dim3(64, 5), 256>>>(b1, W2, b2, out);
}

// round 17
// speedup vs baseline: 1.5214x; 1.5127x over previous
#include <cuda_runtime.h>

// ---------------- scratch (static device globals; no allocation) ----------------
__device__ float g_sig[64 * 4080];          // signature features, (64, 34*120) row-major
__device__ float g_hp[34 * 64 * 512];       // split-K partials of hidden layer

// ---------------- f32x2 packed helpers ----------------
__device__ __forceinline__ unsigned long long ffma2(unsigned long long a,
                                                    unsigned long long b,
                                                    unsigned long long c)
{
    unsigned long long d;
    asm("fma.rn.f32x2 %0, %1, %2, %3;" : "=l"(d) : "l"(a), "l"(b), "l"(c));
    return d;
}
__device__ __forceinline__ unsigned long long pack_dup(float x)
{
    unsigned long long d;
    asm("mov.b64 %0, {%1, %1};" : "=l"(d) : "f"(x));
    return d;
}
__device__ __forceinline__ unsigned long long pack2(float lo, float hi)
{
    unsigned long long d;
    asm("mov.b64 %0, {%1, %2};" : "=l"(d) : "f"(lo), "f"(hi));
    return d;
}
__device__ __forceinline__ void unpack2(unsigned long long v, float& lo, float& hi)
{
    asm("mov.b64 {%0, %1}, %2;" : "=f"(lo), "=f"(hi) : "l"(v));
}

// ================= Kernel 1: depth-4 path signature =================
// 8 paths x 16 chunks, grid 272. Factored Chen step; level-4 accumulator kept
// PACKED as f32x2 pairs over k0/k1 (bit-identical lanes, ~20% fewer issues).
// Combine: levels 0-1 warp shuffles, levels 2-3 smem (2 barriers).

__global__ void __launch_bounds__(128) sig_kernel(const float* __restrict__ inp)
{
    __shared__ float xch[24][121];

    const int tid = threadIdx.x;
    const int pl = tid & 7;
    const int chunk = tid >> 3;
    const int p = blockIdx.x * 8 + pl;
    const int b = p / 34;
    const int vm = p - b * 34;
    const float* base = inp + b * 30600 + vm;

    const int s0 = (chunk * 299) >> 4;
    const int s1 = ((chunk + 1) * 299) >> 4;

    float c1[3], c2[9], c3[27];
    unsigned long long P[27];   // (c4[ij,k=0,l], c4[ij,k=1,l]) at P[ij*3+l]
    float S[27];                //  c4[ij,k=2,l]               at S[ij*3+l]
#pragma unroll
    for (int i = 0; i < 3; i++) c1[i] = 0.f;
#pragma unroll
    for (int i = 0; i < 9; i++) c2[i] = 0.f;
#pragma unroll
    for (int i = 0; i < 27; i++) c3[i] = 0.f;
#pragma unroll
    for (int i = 0; i < 27; i++) { P[i] = 0ull; S[i] = 0.f; }

    float xp[3], xc[3];
#pragma unroll
    for (int c = 0; c < 3; c++) xp[c] = __ldg(base + c * 10200 + s0 * 34);
#pragma unroll
    for (int c = 0; c < 3; c++) xc[c] = __ldg(base + c * 10200 + (s0 + 1) * 34);

    for (int s = s0; s < s1; ++s) {
        int tn = s + 2; if (tn > 299) tn = 299;
        float xn[3];
#pragma unroll
        for (int c = 0; c < 3; c++) xn[c] = __ldg(base + c * 10200 + tn * 34);

        float dx[3], dxh[3], dx3[3], e[3], bq[3], a[3];
#pragma unroll
        for (int i = 0; i < 3; i++) {
            dx[i]  = xc[i] - xp[i];
            dxh[i] = 0.5f * dx[i];
            dx3[i] = (1.0f / 3.0f) * dx[i];
            e[i]  = fmaf(0.25f, dx[i], c1[i]);
            bq[i] = c1[i] + dx3[i];
            a[i]  = c1[i] + dxh[i];
        }
        float q[9], sx[9];
#pragma unroll
        for (int i = 0; i < 3; i++)
#pragma unroll
            for (int j = 0; j < 3; j++) {
                q[i * 3 + j]  = fmaf(e[i],  dx3[j], c2[i * 3 + j]);
                sx[i * 3 + j] = fmaf(bq[i], dxh[j], c2[i * 3 + j]);
            }

        // ---- level 4, packed over k0/k1 ----
        const unsigned long long DXH01 = pack2(dxh[0], dxh[1]);
        unsigned long long DXD[3];
#pragma unroll
        for (int l = 0; l < 3; l++) DXD[l] = pack_dup(dx[l]);
#pragma unroll
        for (int ij = 0; ij < 9; ij++) {
            // RP = (r_k0, r_k1) = (q*dxh0 + c3_k0, q*dxh1 + c3_k1)
            const unsigned long long RP =
                ffma2(pack_dup(q[ij]), DXH01, pack2(c3[ij * 3], c3[ij * 3 + 1]));
            const float r2 = fmaf(q[ij], dxh[2], c3[ij * 3 + 2]);
#pragma unroll
            for (int l = 0; l < 3; l++) {
                P[ij * 3 + l] = ffma2(RP, DXD[l], P[ij * 3 + l]);
                S[ij * 3 + l] = fmaf(r2, dx[l], S[ij * 3 + l]);
            }
        }
        // ---- level 3 ----
#pragma unroll
        for (int i = 0; i < 3; i++)
#pragma unroll
            for (int j = 0; j < 3; j++)
#pragma unroll
                for (int k = 0; k < 3; k++) {
                    const int x = i * 9 + j * 3 + k;
                    c3[x] = fmaf(sx[i * 3 + j], dx[k], c3[x]);
                }
        // ---- level 2 ----
#pragma unroll
        for (int i = 0; i < 3; i++)
#pragma unroll
            for (int j = 0; j < 3; j++)
                c2[i * 3 + j] = fmaf(a[i], dx[j], c2[i * 3 + j]);
        // ---- level 1 ----
#pragma unroll
        for (int i = 0; i < 3; i++) c1[i] += dx[i];

#pragma unroll
        for (int c = 0; c < 3; c++) { xp[c] = xc[c]; xc[c] = xn[c]; }
    }

    // ---- unpack c4 into scalar layout (one-time) ----
    float c4[81];
#pragma unroll
    for (int ij = 0; ij < 9; ij++)
#pragma unroll
        for (int l = 0; l < 3; l++) {
            float lo, hi;
            unpack2(P[ij * 3 + l], lo, hi);
            c4[ij * 9 + 0 + l] = lo;
            c4[ij * 9 + 3 + l] = hi;
            c4[ij * 9 + 6 + l] = S[ij * 3 + l];
        }

    // ---- levels 0-1: shuffle combine (partner = +8, +16 lanes; same warp) ----
#pragma unroll
    for (int d = 0; d < 2; d++) {
        const unsigned delta = 8u << d;
        float bb1[3], bb2[9], bb3[27];
#pragma unroll
        for (int i = 0; i < 3; i++)  bb1[i] = __shfl_down_sync(0xffffffffu, c1[i], delta);
#pragma unroll
        for (int i = 0; i < 9; i++)  bb2[i] = __shfl_down_sync(0xffffffffu, c2[i], delta);
#pragma unroll
        for (int i = 0; i < 27; i++) bb3[i] = __shfl_down_sync(0xffffffffu, c3[i], delta);

#pragma unroll
        for (int i = 0; i < 3; i++)
#pragma unroll
            for (int j = 0; j < 3; j++)
#pragma unroll
                for (int k = 0; k < 3; k++)
#pragma unroll
                    for (int l = 0; l < 3; l++) {
                        const int x = i * 27 + j * 9 + k * 3 + l;
                        const float b4 = __shfl_down_sync(0xffffffffu, c4[x], delta);
                        c4[x] = fmaf(c3[i * 9 + j * 3 + k], bb1[l],
                                fmaf(c2[i * 3 + j], bb2[k * 3 + l],
                                fmaf(c1[i], bb3[j * 9 + k * 3 + l],
                                     c4[x] + b4)));
                    }
#pragma unroll
        for (int i = 0; i < 3; i++)
#pragma unroll
            for (int j = 0; j < 3; j++)
#pragma unroll
                for (int k = 0; k < 3; k++) {
                    const int x = i * 9 + j * 3 + k;
                    c3[x] = fmaf(c2[i * 3 + j], bb1[k],
                            fmaf(c1[i], bb2[j * 3 + k], c3[x] + bb3[x]));
                }
#pragma unroll
        for (int i = 0; i < 3; i++)
#pragma unroll
            for (int j = 0; j < 3; j++)
                c2[i * 3 + j] = fmaf(c1[i], bb1[j], c2[i * 3 + j] + bb2[i * 3 + j]);
#pragma unroll
        for (int i = 0; i < 3; i++) c1[i] += bb1[i];
    }

    // ---- levels 2-3 via smem. Survivors: lanes 0-7 of each warp (chunk=4w). ----
    const int w = tid >> 5;
    const bool lane8 = (tid & 31) < 8;

    if (lane8 && (w & 1)) {                 // level-2 writers: warps 1,3
        float* wr = xch[pl + 8 * (w >> 1)];
#pragma unroll
        for (int i = 0; i < 3; i++) wr[i] = c1[i];
#pragma unroll
        for (int i = 0; i < 9; i++) wr[3 + i] = c2[i];
#pragma unroll
        for (int i = 0; i < 27; i++) wr[12 + i] = c3[i];
#pragma unroll
        for (int i = 0; i < 81; i++) wr[39 + i] = c4[i];
    }
    __syncthreads();
    if (lane8 && !(w & 1)) {                // level-2 readers: warps 0,2
        const float* B = xch[pl + 8 * (w >> 1)];
        float bb1[3], bb2[9], bb3[27];
#pragma unroll
        for (int i = 0; i < 3; i++) bb1[i] = B[i];
#pragma unroll
        for (int i = 0; i < 9; i++) bb2[i] = B[3 + i];
#pragma unroll
        for (int i = 0; i < 27; i++) bb3[i] = B[12 + i];
#pragma unroll
        for (int i = 0; i < 3; i++)
#pragma unroll
            for (int j = 0; j < 3; j++)
#pragma unroll
                for (int k = 0; k < 3; k++)
#pragma unroll
                    for (int l = 0; l < 3; l++) {
                        const int x = i * 27 + j * 9 + k * 3 + l;
                        c4[x] = fmaf(c3[i * 9 + j * 3 + k], bb1[l],
                                fmaf(c2[i * 3 + j], bb2[k * 3 + l],
                                fmaf(c1[i], bb3[j * 9 + k * 3 + l],
                                     c4[x] + B[39 + x])));
                    }
#pragma unroll
        for (int i = 0; i < 3; i++)
#pragma unroll
            for (int j = 0; j < 3; j++)
#pragma unroll
                for (int k = 0; k < 3; k++) {
                    const int x = i * 9 + j * 3 + k;
                    c3[x] = fmaf(c2[i * 3 + j], bb1[k],
                            fmaf(c1[i], bb2[j * 3 + k], c3[x] + bb3[x]));
                }
#pragma unroll
        for (int i = 0; i < 3; i++)
#pragma unroll
            for (int j = 0; j < 3; j++)
                c2[i * 3 + j] = fmaf(c1[i], bb1[j], c2[i * 3 + j] + bb2[i * 3 + j]);
#pragma unroll
        for (int i = 0; i < 3; i++) c1[i] += bb1[i];
    }
    if (lane8 && w == 2) {                  // level-3 writer: warp 2
        float* wr = xch[16 + pl];
#pragma unroll
        for (int i = 0; i < 3; i++) wr[i] = c1[i];
#pragma unroll
        for (int i = 0; i < 9; i++) wr[3 + i] = c2[i];
#pragma unroll
        for (int i = 0; i < 27; i++) wr[12 + i] = c3[i];
#pragma unroll
        for (int i = 0; i < 81; i++) wr[39 + i] = c4[i];
    }
    __syncthreads();
    if (tid < 8) {                          // level-3 reader: warp 0, final store
        const float* B = xch[16 + pl];
        float bb1[3], bb2[9], bb3[27];
#pragma unroll
        for (int i = 0; i < 3; i++) bb1[i] = B[i];
#pragma unroll
        for (int i = 0; i < 9; i++) bb2[i] = B[3 + i];
#pragma unroll
        for (int i = 0; i < 27; i++) bb3[i] = B[12 + i];
#pragma unroll
        for (int i = 0; i < 3; i++)
#pragma unroll
            for (int j = 0; j < 3; j++)
#pragma unroll
                for (int k = 0; k < 3; k++)
#pragma unroll
                    for (int l = 0; l < 3; l++) {
                        const int x = i * 27 + j * 9 + k * 3 + l;
                        c4[x] = fmaf(c3[i * 9 + j * 3 + k], bb1[l],
                                fmaf(c2[i * 3 + j], bb2[k * 3 + l],
                                fmaf(c1[i], bb3[j * 9 + k * 3 + l],
                                     c4[x] + B[39 + x])));
                    }
#pragma unroll
        for (int i = 0; i < 3; i++)
#pragma unroll
            for (int j = 0; j < 3; j++)
#pragma unroll
                for (int k = 0; k < 3; k++) {
                    const int x = i * 9 + j * 3 + k;
                    c3[x] = fmaf(c2[i * 3 + j], bb1[k],
                            fmaf(c1[i], bb2[j * 3 + k], c3[x] + bb3[x]));
                }
#pragma unroll
        for (int i = 0; i < 3; i++)
#pragma unroll
            for (int j = 0; j < 3; j++)
                c2[i * 3 + j] = fmaf(c1[i], bb1[j], c2[i * 3 + j] + bb2[i * 3 + j]);
#pragma unroll
        for (int i = 0; i < 3; i++) c1[i] += bb1[i];

        float* out = g_sig + p * 120;
#pragma unroll
        for (int i = 0; i < 3; i++) out[i] = c1[i];
#pragma unroll
        for (int i = 0; i < 9; i++) out[3 + i] = c2[i];
#pragma unroll
        for (int i = 0; i < 27; i++) out[12 + i] = c3[i];
#pragma unroll
        for (int i = 0; i < 81; i++) out[39 + i] = c4[i];
    }
}

// ================= Kernel 2: h-partials = sig @ W1^T (split-K 34) =================
// (unchanged — at its W1-DRAM floor) Full-K staging, one barrier, FFMA2 loop.

__global__ void __launch_bounds__(128) gemm1_kernel(const float* __restrict__ W1)
{
    __shared__ float As[120][68];
    __shared__ float Bs[120][36];

    const int jt = blockIdx.x;
    const int ks = blockIdx.y;
    const int tid = threadIdx.x;
    const int tx = tid & 7;
    const int ty = tid >> 3;
    const int k0 = ks * 120;
    const int j0 = jt * 32;

    {
        const int arow = tid >> 1;
        const int kh = (tid & 1) * 4;
        const float* Ap = g_sig + arow * 4080 + k0 + kh;
#pragma unroll
        for (int it = 0; it < 15; it++) {
            const float4 v = *(const float4*)(Ap + it * 8);
            const int k = it * 8 + kh;
            As[k + 0][arow] = v.x; As[k + 1][arow] = v.y;
            As[k + 2][arow] = v.z; As[k + 3][arow] = v.w;
        }
    }
    {
        const int jrow = (tid >> 1) & 31;
        const int kh = ((tid >> 6) << 3) + (tid & 1) * 4;
        const float* Bp = W1 + (j0 + jrow) * 4080 + k0 + kh;
#pragma unroll
        for (int it = 0; it < 8; it++) {
            const int k = it * 16 + kh;
            if (k < 120) {
                const float4 v = *(const float4*)(Bp + it * 16);
                Bs[k + 0][jrow] = v.x; Bs[k + 1][jrow] = v.y;
                Bs[k + 2][jrow] = v.z; Bs[k + 3][jrow] = v.w;
            }
        }
    }
    __syncthreads();

    unsigned long long accp[4][2];
#pragma unroll
    for (int r = 0; r < 4; r++) { accp[r][0] = 0ull; accp[r][1] = 0ull; }

#pragma unroll 4
    for (int kk = 0; kk < 120; kk++) {
        const float4 a = *(const float4*)&As[kk][ty * 4];
        const ulonglong2 bp = *(const ulonglong2*)&Bs[kk][tx * 4];
        unsigned long long aa;
        aa = pack_dup(a.x);
        accp[0][0] = ffma2(aa, bp.x, accp[0][0]);
        accp[0][1] = ffma2(aa, bp.y, accp[0][1]);
        aa = pack_dup(a.y);
        accp[1][0] = ffma2(aa, bp.x, accp[1][0]);
        accp[1][1] = ffma2(aa, bp.y, accp[1][1]);
        aa = pack_dup(a.z);
        accp[2][0] = ffma2(aa, bp.x, accp[2][0]);
        accp[2][1] = ffma2(aa, bp.y, accp[2][1]);
        aa = pack_dup(a.w);
        accp[3][0] = ffma2(aa, bp.x, accp[3][0]);
        accp[3][1] = ffma2(aa, bp.y, accp[3][1]);
    }

    float* outp = g_hp + ks * 32768 + j0;
#pragma unroll
    for (int r = 0; r < 4; r++) {
        const unsigned long long v0 = accp[r][0], v1 = accp[r][1];
        float4 v;
        v.x = __uint_as_float((unsigned)(v0 & 0xffffffffu));
        v.y = __uint_as_float((unsigned)(v0 >> 32));
        v.z = __uint_as_float((unsigned)(v1 & 0xffffffffu));
        v.w = __uint_as_float((unsigned)(v1 >> 32));
        *(float4*)(outp + (ty * 4 + r) * 512 + tx * 4) = v;
    }
}

// ====== Kernel 3: out = (sum_s hp_s + b1) @ W2^T + b2, grid (64 rows, 5 j-tiles) ======
// Phase-1 reduce float4: 128 threads x 34 independent float4 loads (MLP 34).

__global__ void __launch_bounds__(256) gemm2_kernel(const float* __restrict__ b1,
                                                    const float* __restrict__ W2,
                                                    const float* __restrict__ b2,
                                                    float* __restrict__ out)
{
    __shared__ float hs[512];
    const int i = blockIdx.x;
    const int jt = blockIdx.y;
    const int tid = threadIdx.x;

    if (tid < 128) {
        const float4* hp = (const float4*)(g_hp + i * 512) + tid;
        float4 a = ((const float4*)b1)[tid];
#pragma unroll
        for (int s = 0; s < 34; s++) {
            const float4 v = hp[s * 8192];          // 32768 floats = 8192 float4
            a.x += v.x; a.y += v.y; a.z += v.z; a.w += v.w;
        }
        ((float4*)hs)[tid] = a;
    }
    __syncthreads();

    const int jl = tid >> 3;
    const int ell = tid & 7;
    if (jl < 31) {
        const int j = jt * 31 + jl;
        const float4* w = (const float4*)(W2 + j * 512) + ell;
        float acc0 = 0.f, acc1 = 0.f;
#pragma unroll
        for (int it = 0; it < 16; it += 2) {
            const float4 w0 = w[it * 8];
            const float4 w1 = w[(it + 1) * 8];
            const float* h0 = &hs[(ell + it * 8) * 4];
            const float* h1 = &hs[(ell + (it + 1) * 8) * 4];
            acc0 = fmaf(h0[0], w0.x, acc0); acc0 = fmaf(h0[1], w0.y, acc0);
            acc0 = fmaf(h0[2], w0.z, acc0); acc0 = fmaf(h0[3], w0.w, acc0);
            acc1 = fmaf(h1[0], w1.x, acc1); acc1 = fmaf(h1[1], w1.y, acc1);
            acc1 = fmaf(h1[2], w1.z, acc1); acc1 = fmaf(h1[3], w1.w, acc1);
        }
        float acc = acc0 + acc1;
#pragma unroll
        for (int m = 1; m < 8; m <<= 1)
            acc += __shfl_xor_sync(0xffffffffu, acc, m);
        if (ell == 0) out[i * 155 + j] = acc + b2[j];
    }
}

// ================================ launch =================================

extern "C" void kernel_launch(void* const* d_in, const int* in_sizes, int n_in,
                              void* d_out, int out_size)
{
    const float* inp = (const float*)d_in[0];
    const float* W1  = (const float*)d_in[1];
    const float* b1  = (const float*)d_in[2];
    const float* W2  = (const float*)d_in[3];
    const float* b2  = (const float*)d_in[4];
    float* out = (float*)d_out;

    sig_kernel<<<272, 128>>>(inp);
    gemm1_kernel<<<dim3(16, 34), 128>>>(W1);
    gemm2_kernel<<<dim3(64, 5), 256>>>(b1, W2, b2, out);
}